// round 6
// baseline (speedup 1.0000x reference)
#include <cuda_runtime.h>
#include <cuda_fp16.h>
#include <cstdint>
#include <cstddef>

// ---------------- problem constants ----------------
#define B_DIM   8192
#define H_DIM   1024
#define NC_DIM  16
#define KTOT    2048          // IN + H

// ---------------- tile config ----------------
#define BM      128
#define BN      128           // 4 gates x 32 (gate-interleaved)
#define BK      64            // 64 fp16 = 128 bytes per row (one SW128 row)
#define STAGES  3
#define NKIT    (KTOT / BK)   // 32
#define NTHREADS 128          // 4 warps, warp tile 64x64

// SMEM layout
#define SM_TILES   1024                          // stage buffers start
#define SA_BYTES   (BM * 128)                    // 16384
#define SB_BYTES   (BN * 128)                    // 16384
#define SSTRIDE    (SA_BYTES + SB_BYTES)         // 32768
#define SMEM_BYTES (SM_TILES + STAGES * SSTRIDE) // 99328  (x2 CTAs = 198656 <= 227KB)

#define EPI_PITCH  132                           // fp32 epilogue staging pitch (mult of 4)

// ---------------- device scratch ----------------
__device__ __align__(16) __half g_A[(size_t)B_DIM * KTOT];      // [x | hx]
__device__ __align__(16) __half g_B[(size_t)4 * H_DIM * KTOT];  // [W_ih | W_hh]
__device__ float g_cin[B_DIM * NC_DIM];
__device__ float g_cfg[B_DIM * NC_DIM];

// ---------------- helpers ----------------
__device__ __forceinline__ uint32_t smem_u32(const void* p) {
    uint32_t a;
    asm("{ .reg .u64 t; cvta.to.shared.u64 t, %1; cvt.u32.u64 %0, t; }" : "=r"(a) : "l"(p));
    return a;
}

__device__ __forceinline__ uint32_t sw128(uint32_t off) { return off ^ ((off >> 3) & 0x70); }

__device__ __forceinline__ void cp_async16(uint32_t dst, const void* src) {
    asm volatile("cp.async.cg.shared.global [%0], [%1], 16;" :: "r"(dst), "l"(src) : "memory");
}
#define CP_COMMIT() asm volatile("cp.async.commit_group;" ::: "memory")
#define CP_WAIT(N)  asm volatile("cp.async.wait_group %0;" :: "n"(N) : "memory")

__device__ __forceinline__ void ldsm4(uint32_t* r, uint32_t addr) {
    asm volatile("ldmatrix.sync.aligned.m8n8.x4.shared.b16 {%0,%1,%2,%3}, [%4];"
                 : "=r"(r[0]), "=r"(r[1]), "=r"(r[2]), "=r"(r[3]) : "r"(addr));
}

__device__ __forceinline__ void mma16816(float* d, const uint32_t* a, const uint32_t* b) {
    asm volatile("mma.sync.aligned.m16n8k16.row.col.f32.f16.f16.f32 "
                 "{%0,%1,%2,%3}, {%4,%5,%6,%7}, {%8,%9}, {%0,%1,%2,%3};"
                 : "+f"(d[0]), "+f"(d[1]), "+f"(d[2]), "+f"(d[3])
                 : "r"(a[0]), "r"(a[1]), "r"(a[2]), "r"(a[3]), "r"(b[0]), "r"(b[1]));
}

__device__ __forceinline__ float sigmoidf_(float x) { return 1.0f / (1.0f + __expf(-x)); }

// ---------------- conversion kernels ----------------
__global__ void convA_kernel(const float* __restrict__ x, const float* __restrict__ hx) {
    size_t i = ((size_t)blockIdx.x * blockDim.x + threadIdx.x) * 8;
    int b = (int)(i >> 11);
    int k = (int)(i & 2047);
    const float* src = (k < 1024) ? (x + (size_t)b * 1024 + k)
                                  : (hx + (size_t)b * 1024 + (k - 1024));
    float4 f0 = *(const float4*)src;
    float4 f1 = *(const float4*)(src + 4);
    __half2 h[4];
    h[0] = __floats2half2_rn(f0.x, f0.y);
    h[1] = __floats2half2_rn(f0.z, f0.w);
    h[2] = __floats2half2_rn(f1.x, f1.y);
    h[3] = __floats2half2_rn(f1.z, f1.w);
    *(uint4*)(g_A + i) = *(uint4*)h;
}

__global__ void convB_kernel(const float* __restrict__ Wih, const float* __restrict__ Whh) {
    size_t i = ((size_t)blockIdx.x * blockDim.x + threadIdx.x) * 8;
    int g = (int)(i >> 11);
    int k = (int)(i & 2047);
    const float* src = (k < 1024) ? (Wih + (size_t)g * 1024 + k)
                                  : (Whh + (size_t)g * 1024 + (k - 1024));
    float4 f0 = *(const float4*)src;
    float4 f1 = *(const float4*)(src + 4);
    __half2 h[4];
    h[0] = __floats2half2_rn(f0.x, f0.y);
    h[1] = __floats2half2_rn(f0.z, f0.w);
    h[2] = __floats2half2_rn(f1.x, f1.y);
    h[3] = __floats2half2_rn(f1.z, f1.w);
    *(uint4*)(g_B + i) = *(uint4*)h;
}

// ---------------- cumsoftmax floors ----------------
__global__ void floors_kernel(const float* __restrict__ ifl, const float* __restrict__ ffl) {
    int b = blockIdx.x * blockDim.x + threadIdx.x;
    if (b >= B_DIM) return;
    float v[16], w[16];
#pragma unroll
    for (int i = 0; i < 16; i++) { v[i] = ifl[b * 16 + i]; w[i] = ffl[b * 16 + i]; }
#pragma unroll
    for (int h = 0; h < 4; h++) {
        float* a = (h < 2) ? (v + 8 * h) : (w + 8 * (h - 2));
        float m = a[0];
#pragma unroll
        for (int i = 1; i < 8; i++) m = fmaxf(m, a[i]);
        float s = 0.f;
#pragma unroll
        for (int i = 0; i < 8; i++) { a[i] = expf(a[i] - m); s += a[i]; }
        float inv = 1.0f / s;
#pragma unroll
        for (int i = 0; i < 8; i++) a[i] *= inv;
    }
    float* cin = g_cin + (size_t)b * 16;
    float* cfg = g_cfg + (size_t)b * 16;
    float run;
    run = 0.f;
#pragma unroll
    for (int i = 0; i < 8; i++) { run += v[i]; cin[i] = run; }          // happy in: prefix
    run = 0.f;
#pragma unroll
    for (int i = 7; i >= 0; i--) { run += v[8 + i]; cin[8 + i] = run; } // sad in: suffix
    run = 0.f;
#pragma unroll
    for (int i = 7; i >= 0; i--) { run += w[i]; cfg[i] = run; }         // happy fg: suffix
    run = 0.f;
#pragma unroll
    for (int i = 0; i < 8; i++) { run += w[8 + i]; cfg[8 + i] = run; }  // sad fg: prefix
}

// ---------------- stage loader ----------------
__device__ __forceinline__ void load_stage(uint32_t sb, int s, int buf, int j, int m0, int tid) {
    const int k0 = s * BK;
    const uint32_t ab = sb + SM_TILES + buf * SSTRIDE;
    const uint32_t bb = ab + SA_BYTES;
#pragma unroll
    for (int i = 0; i < 16; i++) {
        int idx = tid + i * NTHREADS;           // 2048 chunks of 16B
        if (idx < 1024) {                       // A: 128 rows x 8 chunks
            int r = idx >> 3, c = idx & 7;
            const __half* src = g_A + (size_t)(m0 + r) * KTOT + k0 + c * 8;
            cp_async16(ab + sw128((uint32_t)(r * 128 + c * 16)), src);
        } else {                                // B: 128 rows x 8 chunks (gate-interleaved 4x32)
            int v = idx - 1024;
            int r = v >> 3, c = v & 7;
            int grow = (r >> 5) * 1024 + j * 32 + (r & 31);
            const __half* src = g_B + (size_t)grow * KTOT + k0 + c * 8;
            cp_async16(bb + sw128((uint32_t)(r * 128 + c * 16)), src);
        }
    }
}

// ---------------- fused GEMM + ONLSTM epilogue ----------------
__global__ void __launch_bounds__(NTHREADS, 2)
onlstm_kernel(const float* __restrict__ cx,
              const float* __restrict__ bih, const float* __restrict__ bhh,
              float* __restrict__ out_hy, float* __restrict__ out_cy)
{
    extern __shared__ char smem[];
    const int tid = threadIdx.x;
    const int wid = tid >> 5, lane = tid & 31;
    const int j  = blockIdx.x;          // 32-column tile index 0..31
    const int m0 = blockIdx.y * BM;     // batch-row base
    const uint32_t sb = smem_u32(smem);

    float* sbias = (float*)smem;        // 128 floats, region [0,1024)
    if (tid < 128) {
        int grow = (tid >> 5) * 1024 + j * 32 + (tid & 31);
        sbias[tid] = bih[grow] + bhh[grow];
    }

    // prologue: prefetch stages 0..1
#pragma unroll
    for (int p = 0; p < STAGES - 1; p++) {
        load_stage(sb, p, p, j, m0, tid);
        CP_COMMIT();
    }

    const int wm = wid >> 1;            // 0..1  (M)
    const int wn = wid & 1;             // 0..1  (N)

    float acc[4][8][4];                 // 64x64 warp tile: 4 m16 x 8 n8
#pragma unroll
    for (int i = 0; i < 4; i++)
#pragma unroll
        for (int jn = 0; jn < 8; jn++)
#pragma unroll
            for (int t = 0; t < 4; t++) acc[i][jn][t] = 0.f;

    int buf = 0;
    for (int s = 0; s < NKIT; s++) {
        CP_WAIT(STAGES - 2);
        __syncthreads();

        const uint32_t ab = sb + SM_TILES + buf * SSTRIDE;
        const uint32_t bb = ab + SA_BYTES;

#pragma unroll
        for (int ks = 0; ks < 4; ks++) {        // 4 x k16 steps per stage
            uint32_t a_regs[4][4], b_regs[4][4];
#pragma unroll
            for (int i = 0; i < 4; i++) {
                int m  = wm * 64 + i * 16 + (lane & 15);
                int kc = ks * 2 + (lane >> 4);
                ldsm4(a_regs[i], ab + sw128((uint32_t)(m * 128 + kc * 16)));
            }
#pragma unroll
            for (int p = 0; p < 4; p++) {
                int n  = wn * 64 + p * 16 + ((lane >> 4) & 1) * 8 + (lane & 7);
                int kc = ks * 2 + ((lane >> 3) & 1);
                ldsm4(b_regs[p], bb + sw128((uint32_t)(n * 128 + kc * 16)));
            }
#pragma unroll
            for (int i = 0; i < 4; i++)
#pragma unroll
                for (int jn = 0; jn < 8; jn++)
                    mma16816(acc[i][jn], a_regs[i], &b_regs[jn >> 1][(jn & 1) * 2]);
        }

        const int ps = s + STAGES - 1;
        if (ps < NKIT) {
            int pbuf = buf + (STAGES - 1);
            if (pbuf >= STAGES) pbuf -= STAGES;
            load_stage(sb, ps, pbuf, j, m0, tid);
        }
        CP_COMMIT();
        if (++buf == STAGES) buf = 0;
    }

    __syncthreads();

    // stage accumulators (raw gates, no bias yet) into SMEM, overlaying tile buffers
    float* epi = (float*)(smem + SM_TILES);
#pragma unroll
    for (int i = 0; i < 4; i++) {
#pragma unroll
        for (int jn = 0; jn < 8; jn++) {
            int r = wm * 64 + i * 16 + (lane >> 2);
            int c = wn * 64 + jn * 8 + (lane & 3) * 2;
            *(float2*)&epi[r * EPI_PITCH + c]       = make_float2(acc[i][jn][0], acc[i][jn][1]);
            *(float2*)&epi[(r + 8) * EPI_PITCH + c] = make_float2(acc[i][jn][2], acc[i][jn][3]);
        }
    }
    __syncthreads();

    // fused ONLSTM epilogue: this CTA owns gate columns [j*32, j*32+32) of each gate.
    // 128 rows x 32 cols = 4096 floats = 1024 float4 groups; 8 groups per row.
    const int nc = j >> 1;              // head-chunk index (32-col tile -> 64-col chunk)
#pragma unroll
    for (int t = 0; t < 8; t++) {
        int idx = tid + t * NTHREADS;      // 0..1023
        int r = idx >> 3;                  // 0..127
        int c4 = (idx & 7) * 4;            // 0,4,...,28
        int b = m0 + r;
        float ci = g_cin[b * 16 + nc];
        float cf = g_cfg[b * 16 + nc];
        float ov = cf * ci;
        float fa = cf - ov, ia = ci - ov;
        float4 go = *(float4*)&epi[r * EPI_PITCH + c4];
        float4 gc = *(float4*)&epi[r * EPI_PITCH + 32 + c4];
        float4 gi = *(float4*)&epi[r * EPI_PITCH + 64 + c4];
        float4 gf = *(float4*)&epi[r * EPI_PITCH + 96 + c4];
        size_t g = (size_t)b * H_DIM + j * 32 + c4;
        float4 cxv = *(const float4*)&cx[g];
        float4 hyv, cyv;
        {
            float o  = sigmoidf_(go.x + sbias[c4]);
            float ce = tanhf    (gc.x + sbias[32 + c4]);
            float ig = sigmoidf_(gi.x + sbias[64 + c4]) * ov + ia;
            float fg = sigmoidf_(gf.x + sbias[96 + c4]) * ov + fa;
            cyv.x = fg * cxv.x + ig * ce; hyv.x = o * tanhf(cyv.x);
        }
        {
            float o  = sigmoidf_(go.y + sbias[c4 + 1]);
            float ce = tanhf    (gc.y + sbias[33 + c4]);
            float ig = sigmoidf_(gi.y + sbias[65 + c4]) * ov + ia;
            float fg = sigmoidf_(gf.y + sbias[97 + c4]) * ov + fa;
            cyv.y = fg * cxv.y + ig * ce; hyv.y = o * tanhf(cyv.y);
        }
        {
            float o  = sigmoidf_(go.z + sbias[c4 + 2]);
            float ce = tanhf    (gc.z + sbias[34 + c4]);
            float ig = sigmoidf_(gi.z + sbias[66 + c4]) * ov + ia;
            float fg = sigmoidf_(gf.z + sbias[98 + c4]) * ov + fa;
            cyv.z = fg * cxv.z + ig * ce; hyv.z = o * tanhf(cyv.z);
        }
        {
            float o  = sigmoidf_(go.w + sbias[c4 + 3]);
            float ce = tanhf    (gc.w + sbias[35 + c4]);
            float ig = sigmoidf_(gi.w + sbias[67 + c4]) * ov + ia;
            float fg = sigmoidf_(gf.w + sbias[99 + c4]) * ov + fa;
            cyv.w = fg * cxv.w + ig * ce; hyv.w = o * tanhf(cyv.w);
        }
        *(float4*)&out_hy[g] = hyv;
        if (out_cy) *(float4*)&out_cy[g] = cyv;
    }
}

// ---------------- launch ----------------
extern "C" void kernel_launch(void* const* d_in, const int* in_sizes, int n_in,
                              void* d_out, int out_size) {
    const float* x   = (const float*)d_in[0];
    const float* hx  = (const float*)d_in[1];
    const float* cx  = (const float*)d_in[2];
    const float* ifl = (const float*)d_in[3];
    const float* ffl = (const float*)d_in[4];
    const float* Wih = (const float*)d_in[5];
    const float* bih = (const float*)d_in[6];
    const float* Whh = (const float*)d_in[7];
    const float* bhh = (const float*)d_in[8];

    float* out = (float*)d_out;
    float* out_hy = out;
    float* out_cy = ((long long)out_size >= 2LL * B_DIM * H_DIM)
                        ? out + (size_t)B_DIM * H_DIM : nullptr;

    convA_kernel<<<(B_DIM * (size_t)KTOT / 8 + 255) / 256, 256>>>(x, hx);
    convB_kernel<<<(4 * (size_t)H_DIM * KTOT / 8 + 255) / 256, 256>>>(Wih, Whh);
    floors_kernel<<<B_DIM / 256, 256>>>(ifl, ffl);

    cudaFuncSetAttribute(onlstm_kernel,
                         cudaFuncAttributeMaxDynamicSharedMemorySize, SMEM_BYTES);

    dim3 grid(H_DIM / 32, B_DIM / BM);   // (32 j-tiles, 64 m-tiles); j fastest -> A-tile L2 reuse
    onlstm_kernel<<<grid, NTHREADS, SMEM_BYTES>>>(cx, bih, bhh, out_hy, out_cy);
}

// round 7
// speedup vs baseline: 1.0676x; 1.0676x over previous
#include <cuda_runtime.h>
#include <cuda_fp16.h>
#include <cstdint>
#include <cstddef>

// ---------------- problem constants ----------------
#define B_DIM   8192
#define H_DIM   1024
#define NC_DIM  16
#define KTOT    2048          // IN + H

// ---------------- tile config ----------------
#define BM      128
#define BN      64            // 4 gates x 16 (gate-interleaved)
#define BK      64            // 64 fp16 = 128 bytes per row (one SW128 row)
#define STAGES  3
#define NKIT    (KTOT / BK)   // 32
#define NTHREADS 128          // 4 warps, warp tile 64x32

// SMEM layout
#define SM_TILES   1024                          // stage buffers start
#define SA_BYTES   (BM * 128)                    // 16384
#define SB_BYTES   (BN * 128)                    // 8192
#define SSTRIDE    (SA_BYTES + SB_BYTES)         // 24576
#define SMEM_BYTES (SM_TILES + STAGES * SSTRIDE) // 74752 (x3 CTAs = 224256 <= 228KB)

#define EPI_PITCH  68                            // fp32 epilogue staging pitch (mult of 4)

// ---------------- device scratch ----------------
__device__ __align__(16) __half g_A[(size_t)B_DIM * KTOT];      // [x | hx]
__device__ __align__(16) __half g_B[(size_t)4 * H_DIM * KTOT];  // [W_ih | W_hh]
__device__ float g_cin[B_DIM * NC_DIM];
__device__ float g_cfg[B_DIM * NC_DIM];

// ---------------- helpers ----------------
__device__ __forceinline__ uint32_t smem_u32(const void* p) {
    uint32_t a;
    asm("{ .reg .u64 t; cvta.to.shared.u64 t, %1; cvt.u32.u64 %0, t; }" : "=r"(a) : "l"(p));
    return a;
}

__device__ __forceinline__ uint32_t sw128(uint32_t off) { return off ^ ((off >> 3) & 0x70); }

__device__ __forceinline__ void cp_async16(uint32_t dst, const void* src) {
    asm volatile("cp.async.cg.shared.global [%0], [%1], 16;" :: "r"(dst), "l"(src) : "memory");
}
#define CP_COMMIT() asm volatile("cp.async.commit_group;" ::: "memory")
#define CP_WAIT(N)  asm volatile("cp.async.wait_group %0;" :: "n"(N) : "memory")

__device__ __forceinline__ void ldsm4(uint32_t* r, uint32_t addr) {
    asm volatile("ldmatrix.sync.aligned.m8n8.x4.shared.b16 {%0,%1,%2,%3}, [%4];"
                 : "=r"(r[0]), "=r"(r[1]), "=r"(r[2]), "=r"(r[3]) : "r"(addr));
}

__device__ __forceinline__ void mma16816(float* d, const uint32_t* a, const uint32_t* b) {
    asm volatile("mma.sync.aligned.m16n8k16.row.col.f32.f16.f16.f32 "
                 "{%0,%1,%2,%3}, {%4,%5,%6,%7}, {%8,%9}, {%0,%1,%2,%3};"
                 : "+f"(d[0]), "+f"(d[1]), "+f"(d[2]), "+f"(d[3])
                 : "r"(a[0]), "r"(a[1]), "r"(a[2]), "r"(a[3]), "r"(b[0]), "r"(b[1]));
}

__device__ __forceinline__ float sigmoidf_(float x) { return 1.0f / (1.0f + __expf(-x)); }

// ---------------- conversion kernels ----------------
__global__ void convA_kernel(const float* __restrict__ x, const float* __restrict__ hx) {
    size_t i = ((size_t)blockIdx.x * blockDim.x + threadIdx.x) * 8;
    int b = (int)(i >> 11);
    int k = (int)(i & 2047);
    const float* src = (k < 1024) ? (x + (size_t)b * 1024 + k)
                                  : (hx + (size_t)b * 1024 + (k - 1024));
    float4 f0 = *(const float4*)src;
    float4 f1 = *(const float4*)(src + 4);
    __half2 h[4];
    h[0] = __floats2half2_rn(f0.x, f0.y);
    h[1] = __floats2half2_rn(f0.z, f0.w);
    h[2] = __floats2half2_rn(f1.x, f1.y);
    h[3] = __floats2half2_rn(f1.z, f1.w);
    *(uint4*)(g_A + i) = *(uint4*)h;
}

__global__ void convB_kernel(const float* __restrict__ Wih, const float* __restrict__ Whh) {
    size_t i = ((size_t)blockIdx.x * blockDim.x + threadIdx.x) * 8;
    int g = (int)(i >> 11);
    int k = (int)(i & 2047);
    const float* src = (k < 1024) ? (Wih + (size_t)g * 1024 + k)
                                  : (Whh + (size_t)g * 1024 + (k - 1024));
    float4 f0 = *(const float4*)src;
    float4 f1 = *(const float4*)(src + 4);
    __half2 h[4];
    h[0] = __floats2half2_rn(f0.x, f0.y);
    h[1] = __floats2half2_rn(f0.z, f0.w);
    h[2] = __floats2half2_rn(f1.x, f1.y);
    h[3] = __floats2half2_rn(f1.z, f1.w);
    *(uint4*)(g_B + i) = *(uint4*)h;
}

// ---------------- cumsoftmax floors ----------------
__global__ void floors_kernel(const float* __restrict__ ifl, const float* __restrict__ ffl) {
    int b = blockIdx.x * blockDim.x + threadIdx.x;
    if (b >= B_DIM) return;
    float v[16], w[16];
#pragma unroll
    for (int i = 0; i < 16; i++) { v[i] = ifl[b * 16 + i]; w[i] = ffl[b * 16 + i]; }
#pragma unroll
    for (int h = 0; h < 4; h++) {
        float* a = (h < 2) ? (v + 8 * h) : (w + 8 * (h - 2));
        float m = a[0];
#pragma unroll
        for (int i = 1; i < 8; i++) m = fmaxf(m, a[i]);
        float s = 0.f;
#pragma unroll
        for (int i = 0; i < 8; i++) { a[i] = expf(a[i] - m); s += a[i]; }
        float inv = 1.0f / s;
#pragma unroll
        for (int i = 0; i < 8; i++) a[i] *= inv;
    }
    float* cin = g_cin + (size_t)b * 16;
    float* cfg = g_cfg + (size_t)b * 16;
    float run;
    run = 0.f;
#pragma unroll
    for (int i = 0; i < 8; i++) { run += v[i]; cin[i] = run; }          // happy in: prefix
    run = 0.f;
#pragma unroll
    for (int i = 7; i >= 0; i--) { run += v[8 + i]; cin[8 + i] = run; } // sad in: suffix
    run = 0.f;
#pragma unroll
    for (int i = 7; i >= 0; i--) { run += w[i]; cfg[i] = run; }         // happy fg: suffix
    run = 0.f;
#pragma unroll
    for (int i = 0; i < 8; i++) { run += w[8 + i]; cfg[8 + i] = run; }  // sad fg: prefix
}

// ---------------- stage loader ----------------
__device__ __forceinline__ void load_stage(uint32_t sb, int s, int buf, int j, int m0, int tid) {
    const int k0 = s * BK;
    const uint32_t ab = sb + SM_TILES + buf * SSTRIDE;
    const uint32_t bb = ab + SA_BYTES;
#pragma unroll
    for (int i = 0; i < 12; i++) {
        int idx = tid + i * NTHREADS;           // 1536 chunks of 16B
        if (idx < 1024) {                       // A: 128 rows x 8 chunks
            int r = idx >> 3, c = idx & 7;
            const __half* src = g_A + (size_t)(m0 + r) * KTOT + k0 + c * 8;
            cp_async16(ab + sw128((uint32_t)(r * 128 + c * 16)), src);
        } else {                                // B: 64 rows x 8 chunks (gate-interleaved 4x16)
            int v = idx - 1024;
            int r = v >> 3, c = v & 7;
            int grow = (r >> 4) * 1024 + j * 16 + (r & 15);
            const __half* src = g_B + (size_t)grow * KTOT + k0 + c * 8;
            cp_async16(bb + sw128((uint32_t)(r * 128 + c * 16)), src);
        }
    }
}

// ---------------- fused GEMM + ONLSTM epilogue ----------------
__global__ void __launch_bounds__(NTHREADS, 3)
onlstm_kernel(const float* __restrict__ cx,
              const float* __restrict__ bih, const float* __restrict__ bhh,
              float* __restrict__ out_hy, float* __restrict__ out_cy)
{
    extern __shared__ char smem[];
    const int tid = threadIdx.x;
    const int wid = tid >> 5, lane = tid & 31;
    const int j  = blockIdx.x;          // 16-column tile index 0..63
    const int m0 = blockIdx.y * BM;     // batch-row base
    const uint32_t sb = smem_u32(smem);

    float* sbias = (float*)smem;        // 64 floats, region [0,1024)
    if (tid < 64) {
        int grow = (tid >> 4) * 1024 + j * 16 + (tid & 15);
        sbias[tid] = bih[grow] + bhh[grow];
    }

    // prologue: prefetch stages 0..1
#pragma unroll
    for (int p = 0; p < STAGES - 1; p++) {
        load_stage(sb, p, p, j, m0, tid);
        CP_COMMIT();
    }

    const int wm = wid >> 1;            // 0..1  (M)
    const int wn = wid & 1;             // 0..1  (N)

    float acc[4][4][4];                 // 64x32 warp tile: 4 m16 x 4 n8
#pragma unroll
    for (int i = 0; i < 4; i++)
#pragma unroll
        for (int jn = 0; jn < 4; jn++)
#pragma unroll
            for (int t = 0; t < 4; t++) acc[i][jn][t] = 0.f;

    int buf = 0;
    for (int s = 0; s < NKIT; s++) {
        CP_WAIT(STAGES - 2);
        __syncthreads();

        const uint32_t ab = sb + SM_TILES + buf * SSTRIDE;
        const uint32_t bb = ab + SA_BYTES;

#pragma unroll
        for (int ks = 0; ks < 4; ks++) {        // 4 x k16 steps per stage
            uint32_t a_regs[4][4], b_regs[2][4];
#pragma unroll
            for (int i = 0; i < 4; i++) {
                int m  = wm * 64 + i * 16 + (lane & 15);
                int kc = ks * 2 + (lane >> 4);
                ldsm4(a_regs[i], ab + sw128((uint32_t)(m * 128 + kc * 16)));
            }
#pragma unroll
            for (int p = 0; p < 2; p++) {
                int n  = wn * 32 + p * 16 + ((lane >> 4) & 1) * 8 + (lane & 7);
                int kc = ks * 2 + ((lane >> 3) & 1);
                ldsm4(b_regs[p], bb + sw128((uint32_t)(n * 128 + kc * 16)));
            }
#pragma unroll
            for (int i = 0; i < 4; i++)
#pragma unroll
                for (int jn = 0; jn < 4; jn++)
                    mma16816(acc[i][jn], a_regs[i], &b_regs[jn >> 1][(jn & 1) * 2]);
        }

        const int ps = s + STAGES - 1;
        if (ps < NKIT) {
            int pbuf = buf + (STAGES - 1);
            if (pbuf >= STAGES) pbuf -= STAGES;
            load_stage(sb, ps, pbuf, j, m0, tid);
        }
        CP_COMMIT();
        if (++buf == STAGES) buf = 0;
    }

    __syncthreads();

    // stage accumulators (raw gates, no bias yet) into SMEM, overlaying tile buffers
    float* epi = (float*)(smem + SM_TILES);
#pragma unroll
    for (int i = 0; i < 4; i++) {
#pragma unroll
        for (int jn = 0; jn < 4; jn++) {
            int r = wm * 64 + i * 16 + (lane >> 2);
            int c = wn * 32 + jn * 8 + (lane & 3) * 2;
            *(float2*)&epi[r * EPI_PITCH + c]       = make_float2(acc[i][jn][0], acc[i][jn][1]);
            *(float2*)&epi[(r + 8) * EPI_PITCH + c] = make_float2(acc[i][jn][2], acc[i][jn][3]);
        }
    }
    __syncthreads();

    // fused ONLSTM epilogue: this CTA owns gate columns [j*16, j*16+16) of each gate.
    // 128 rows x 16 cols = 2048 floats = 512 float4 groups; 4 groups per row.
    const int nc = j >> 2;              // head-chunk index (16-col tile -> 64-col chunk)
#pragma unroll
    for (int t = 0; t < 4; t++) {
        int idx = tid + t * NTHREADS;      // 0..511
        int r = idx >> 2;                  // 0..127
        int c4 = (idx & 3) * 4;            // 0,4,8,12
        int b = m0 + r;
        float ci = g_cin[b * 16 + nc];
        float cf = g_cfg[b * 16 + nc];
        float ov = cf * ci;
        float fa = cf - ov, ia = ci - ov;
        float4 go = *(float4*)&epi[r * EPI_PITCH + c4];
        float4 gc = *(float4*)&epi[r * EPI_PITCH + 16 + c4];
        float4 gi = *(float4*)&epi[r * EPI_PITCH + 32 + c4];
        float4 gf = *(float4*)&epi[r * EPI_PITCH + 48 + c4];
        size_t g = (size_t)b * H_DIM + j * 16 + c4;
        float4 cxv = *(const float4*)&cx[g];
        float4 hyv, cyv;
        {
            float o  = sigmoidf_(go.x + sbias[c4]);
            float ce = tanhf    (gc.x + sbias[16 + c4]);
            float ig = sigmoidf_(gi.x + sbias[32 + c4]) * ov + ia;
            float fg = sigmoidf_(gf.x + sbias[48 + c4]) * ov + fa;
            cyv.x = fg * cxv.x + ig * ce; hyv.x = o * tanhf(cyv.x);
        }
        {
            float o  = sigmoidf_(go.y + sbias[c4 + 1]);
            float ce = tanhf    (gc.y + sbias[17 + c4]);
            float ig = sigmoidf_(gi.y + sbias[33 + c4]) * ov + ia;
            float fg = sigmoidf_(gf.y + sbias[49 + c4]) * ov + fa;
            cyv.y = fg * cxv.y + ig * ce; hyv.y = o * tanhf(cyv.y);
        }
        {
            float o  = sigmoidf_(go.z + sbias[c4 + 2]);
            float ce = tanhf    (gc.z + sbias[18 + c4]);
            float ig = sigmoidf_(gi.z + sbias[34 + c4]) * ov + ia;
            float fg = sigmoidf_(gf.z + sbias[50 + c4]) * ov + fa;
            cyv.z = fg * cxv.z + ig * ce; hyv.z = o * tanhf(cyv.z);
        }
        {
            float o  = sigmoidf_(go.w + sbias[c4 + 3]);
            float ce = tanhf    (gc.w + sbias[19 + c4]);
            float ig = sigmoidf_(gi.w + sbias[35 + c4]) * ov + ia;
            float fg = sigmoidf_(gf.w + sbias[51 + c4]) * ov + fa;
            cyv.w = fg * cxv.w + ig * ce; hyv.w = o * tanhf(cyv.w);
        }
        *(float4*)&out_hy[g] = hyv;
        if (out_cy) *(float4*)&out_cy[g] = cyv;
    }
}

// ---------------- launch ----------------
extern "C" void kernel_launch(void* const* d_in, const int* in_sizes, int n_in,
                              void* d_out, int out_size) {
    const float* x   = (const float*)d_in[0];
    const float* hx  = (const float*)d_in[1];
    const float* cx  = (const float*)d_in[2];
    const float* ifl = (const float*)d_in[3];
    const float* ffl = (const float*)d_in[4];
    const float* Wih = (const float*)d_in[5];
    const float* bih = (const float*)d_in[6];
    const float* Whh = (const float*)d_in[7];
    const float* bhh = (const float*)d_in[8];

    float* out = (float*)d_out;
    float* out_hy = out;
    float* out_cy = ((long long)out_size >= 2LL * B_DIM * H_DIM)
                        ? out + (size_t)B_DIM * H_DIM : nullptr;

    convA_kernel<<<(B_DIM * (size_t)KTOT / 8 + 255) / 256, 256>>>(x, hx);
    convB_kernel<<<(4 * (size_t)H_DIM * KTOT / 8 + 255) / 256, 256>>>(Wih, Whh);
    floors_kernel<<<B_DIM / 256, 256>>>(ifl, ffl);

    cudaFuncSetAttribute(onlstm_kernel,
                         cudaFuncAttributeMaxDynamicSharedMemorySize, SMEM_BYTES);

    dim3 grid(H_DIM / 16, B_DIM / BM);   // (64 j-tiles, 64 m-tiles); j fastest -> A-tile L2 reuse
    onlstm_kernel<<<grid, NTHREADS, SMEM_BYTES>>>(cx, bih, bhh, out_hy, out_cy);
}